// round 12
// baseline (speedup 1.0000x reference)
#include <cuda_runtime.h>
#include <cuda_fp16.h>
#include <cstdint>

// Shapes (fixed for this problem)
constexpr int MDIM = 4096;   // B*S
constexpr int KDIM = 4096;
constexpr int NDIM = 11008;
constexpr int GRP  = 128;

// -----------------------------------------------------------------------
// Scratch (allocation-free rule: __device__ globals)
//   g_A: [M][K] fp16 = fp16(x)
//   g_B: [N][K] fp16 = fp16((v - z) * scale)   (k-contiguous rows)
// -----------------------------------------------------------------------
__device__ __half g_A[(size_t)MDIM * KDIM];
__device__ __half g_B[(size_t)NDIM * KDIM];

// ========================= PTX helpers =========================
__device__ __forceinline__ uint32_t smem_u32(const void* p) {
    return (uint32_t)__cvta_generic_to_shared(p);
}
__device__ __forceinline__ void cp_async16(uint32_t smem, const void* gmem) {
    asm volatile("cp.async.cg.shared.global [%0], [%1], 16;\n"
                 :: "r"(smem), "l"(gmem));
}
__device__ __forceinline__ void cp_commit() {
    asm volatile("cp.async.commit_group;\n");
}
__device__ __forceinline__ void cp_wait1() {
    asm volatile("cp.async.wait_group 1;\n");
}
__device__ __forceinline__ void ldmatrix_x4(uint32_t& r0, uint32_t& r1,
                                            uint32_t& r2, uint32_t& r3,
                                            uint32_t addr) {
    asm volatile("ldmatrix.sync.aligned.m8n8.x4.shared.b16 {%0,%1,%2,%3}, [%4];\n"
                 : "=r"(r0), "=r"(r1), "=r"(r2), "=r"(r3) : "r"(addr));
}
__device__ __forceinline__ void mma_f16(float& c0, float& c1, float& c2, float& c3,
                                        uint32_t a0, uint32_t a1, uint32_t a2, uint32_t a3,
                                        uint32_t b0, uint32_t b1) {
    asm volatile("mma.sync.aligned.m16n8k16.row.col.f32.f16.f16.f32 "
                 "{%0,%1,%2,%3}, {%4,%5,%6,%7}, {%8,%9}, {%0,%1,%2,%3};\n"
                 : "+f"(c0), "+f"(c1), "+f"(c2), "+f"(c3)
                 : "r"(a0), "r"(a1), "r"(a2), "r"(a3), "r"(b0), "r"(b1));
}

// ========================= Kernel 1: merged prep (R10, unchanged) =======
constexpr int CONV_BLOCKS = (MDIM * KDIM / 8) / 256;          // 8192
constexpr int DQ_NT = NDIM / 64;                               // 172
constexpr int DQ_KT = KDIM / 256;                              // 16
constexpr int DQ_BLOCKS = DQ_NT * DQ_KT;                       // 2752

constexpr int SH_STRIDE = 264;   // halfs per row (256 + 8 pad); chunk-swizzled

__global__ void prep_kernel(const float* __restrict__ x,
                            const int* __restrict__ qw,
                            const int* __restrict__ qz,
                            const float* __restrict__ sc) {
    const int tid = threadIdx.x;

    if (blockIdx.x < CONV_BLOCKS) {
        size_t i = (size_t)blockIdx.x * 256 + tid;
        const float4* x4 = reinterpret_cast<const float4*>(x);
        float4 a = x4[2 * i];
        float4 b = x4[2 * i + 1];
        __half2 h0 = __floats2half2_rn(a.x, a.y);
        __half2 h1 = __floats2half2_rn(a.z, a.w);
        __half2 h2 = __floats2half2_rn(b.x, b.y);
        __half2 h3 = __floats2half2_rn(b.z, b.w);
        uint4 o;
        o.x = *reinterpret_cast<uint32_t*>(&h0);
        o.y = *reinterpret_cast<uint32_t*>(&h1);
        o.z = *reinterpret_cast<uint32_t*>(&h2);
        o.w = *reinterpret_cast<uint32_t*>(&h3);
        reinterpret_cast<uint4*>(g_A)[i] = o;
        return;
    }

    __shared__ __half sh[64 * SH_STRIDE];
    __shared__ float  s_scale[2][64];
    __shared__ int    s_z[2][8];

    const int t  = blockIdx.x - CONV_BLOCKS;
    const int n0 = (t % DQ_NT) * 64;
    const int k0 = (t / DQ_NT) * 256;
    const int g0 = k0 / GRP;
    const int pw = NDIM / 8;

    if (tid < 128) {
        int g  = tid >> 6;
        int nl = tid & 63;
        s_scale[g][nl] = sc[(size_t)(g0 + g) * NDIM + n0 + nl];
    }
    if (tid < 16) {
        s_z[tid >> 3][tid & 7] = qz[(size_t)(g0 + (tid >> 3)) * pw + n0 / 8 + (tid & 7)];
    }
    __syncthreads();

    const int p  = tid & 7;
    const int kq = tid >> 3;
    const int grp = kq >> 4;
    const int zp = s_z[grp][p];

    const int shifts[8] = {0, 16, 4, 20, 8, 24, 12, 28};
    float sc8[8];
    int   z8[8];
#pragma unroll
    for (int j = 0; j < 8; j++) {
        sc8[j] = s_scale[grp][p * 8 + j];
        z8[j]  = (zp >> shifts[j]) & 0xF;
    }

    __half rows[8][8];
#pragma unroll
    for (int d = 0; d < 8; d++) {
        int packed = qw[(size_t)(k0 + kq * 8 + d) * pw + n0 / 8 + p];
#pragma unroll
        for (int j = 0; j < 8; j++) {
            int v = (packed >> shifts[j]) & 0xF;
            rows[j][d] = __float2half_rn((float)(v - z8[j]) * sc8[j]);
        }
    }

    const int chnk = kq ^ p;
#pragma unroll
    for (int j = 0; j < 8; j++) {
        int row = p * 8 + j;
        *reinterpret_cast<uint4*>(&sh[row * SH_STRIDE + chnk * 8]) =
            *reinterpret_cast<const uint4*>(&rows[j][0]);
    }
    __syncthreads();

#pragma unroll
    for (int it = 0; it < 8; it++) {
        int u   = tid + it * 256;
        int row = u >> 5;
        int c   = u & 31;
        int cs  = c ^ ((row >> 3) & 7);
        uint4 v = *reinterpret_cast<const uint4*>(&sh[row * SH_STRIDE + cs * 8]);
        *reinterpret_cast<uint4*>(&g_B[(size_t)(n0 + row) * KDIM + k0 + c * 8]) = v;
    }
}

// ========================= Kernel 2: fp16 GEMM (mma.sync) ================
// BM=128 BN=64 BK=32, 256 threads (4m x 2n warps, warp tile 32x32),
// padded LDA=40 smem (conflict-free), 3-stage cp.async, TARGET 4 CTAs/SM.
constexpr int BM = 128, BN = 64, BK = 32;
constexpr int STAGES = 3;
constexpr int LDA = BK + 8;                      // 40 halfs = 80B rows
constexpr int A_STAGE_ELEMS = BM * LDA;          // 5120 halfs = 10240B
constexpr int B_STAGE_ELEMS = BN * LDA;          // 2560 halfs = 5120B
constexpr int STAGE_ELEMS   = A_STAGE_ELEMS + B_STAGE_ELEMS;  // 7680
constexpr int GEMM_SMEM = STAGES * STAGE_ELEMS * 2;           // 46080 B

__global__ __launch_bounds__(256, 4)
void gemm_f16_kernel(const float* __restrict__ bias, float* __restrict__ out) {
    extern __shared__ __half smem[];

    const int tid  = threadIdx.x;
    const int lane = tid & 31;
    const int warp = tid >> 5;
    const int m0 = blockIdx.x * BM;       // m-major: wave covers all m tiles
    const int n0 = blockIdx.y * BN;
    const int wm = (warp & 3) * 32;       // 0/32/64/96
    const int wn = (warp >> 2) * 32;      // 0/32

    float acc[2][4][4];
#pragma unroll
    for (int a = 0; a < 2; a++)
#pragma unroll
        for (int b = 0; b < 4; b++)
#pragma unroll
            for (int c = 0; c < 4; c++) acc[a][b][c] = 0.0f;

    constexpr int T = KDIM / BK;  // 128

    // FIXED loader (R4-verified pattern): rows have 4 x 16B chunks.
    // A: 128 rows x 4 chunks = 512 -> 2 per thread; B: 64 x 4 = 256 -> 1.
    auto load_stage = [&](int s, int bk) {
        uint32_t base = smem_u32(smem) + (uint32_t)(s * STAGE_ELEMS) * 2;
#pragma unroll
        for (int i = 0; i < 2; i++) {
            int id = tid + i * 256;       // 0..511
            int r = id >> 2, c = id & 3;
            cp_async16(base + (uint32_t)(r * LDA + c * 8) * 2,
                       &g_A[(size_t)(m0 + r) * KDIM + bk + c * 8]);
        }
        {
            int r = tid >> 2, c = tid & 3;
            cp_async16(base + (uint32_t)(A_STAGE_ELEMS + r * LDA + c * 8) * 2,
                       &g_B[(size_t)(n0 + r) * KDIM + bk + c * 8]);
        }
    };

    load_stage(0, 0);  cp_commit();
    load_stage(1, BK); cp_commit();

    // base smem addrs for ldmatrix (bytes)
    const uint32_t aBase = smem_u32(smem) +
        (uint32_t)((wm + (lane & 15)) * LDA) * 2 + ((uint32_t)(lane >> 4) << 4);
    const uint32_t bBase = smem_u32(smem) + (uint32_t)A_STAGE_ELEMS * 2 +
        (uint32_t)((wn + ((lane >> 4) << 3) + (lane & 7)) * LDA) * 2 +
        (((uint32_t)(lane >> 3) & 1) << 4);

    int s = 0;
    for (int t = 0; t < T; t++) {
        cp_wait1();
        __syncthreads();

        if (t + 2 < T) {
            int ns = s + 2;
            if (ns >= STAGES) ns -= STAGES;
            load_stage(ns, (t + 2) * BK);
        }
        cp_commit();

        const uint32_t so = (uint32_t)(s * STAGE_ELEMS) * 2;

#pragma unroll
        for (int ks = 0; ks < 2; ks++) {
            uint32_t afr[2][4];
            uint32_t bfr[4][2];
#pragma unroll
            for (int mt = 0; mt < 2; mt++)
                ldmatrix_x4(afr[mt][0], afr[mt][1], afr[mt][2], afr[mt][3],
                            aBase + so + (uint32_t)(mt * 16 * LDA * 2) + ks * 32);
#pragma unroll
            for (int nt2 = 0; nt2 < 2; nt2++)
                ldmatrix_x4(bfr[nt2 * 2][0], bfr[nt2 * 2][1],
                            bfr[nt2 * 2 + 1][0], bfr[nt2 * 2 + 1][1],
                            bBase + so + (uint32_t)(nt2 * 16 * LDA * 2) + ks * 32);
#pragma unroll
            for (int mt = 0; mt < 2; mt++)
#pragma unroll
                for (int nt = 0; nt < 4; nt++)
                    mma_f16(acc[mt][nt][0], acc[mt][nt][1], acc[mt][nt][2], acc[mt][nt][3],
                            afr[mt][0], afr[mt][1], afr[mt][2], afr[mt][3],
                            bfr[nt][0], bfr[nt][1]);
        }
        if (++s == STAGES) s = 0;
    }

    // --- epilogue: += bias, fp32 stores ---
#pragma unroll
    for (int mt = 0; mt < 2; mt++) {
#pragma unroll
        for (int nt = 0; nt < 4; nt++) {
            int r = m0 + wm + mt * 16 + (lane >> 2);
            int c = n0 + wn + nt * 8 + (lane & 3) * 2;
            float2 bv = *reinterpret_cast<const float2*>(&bias[c]);
            float2 v0 = {acc[mt][nt][0] + bv.x, acc[mt][nt][1] + bv.y};
            float2 v1 = {acc[mt][nt][2] + bv.x, acc[mt][nt][3] + bv.y};
            *reinterpret_cast<float2*>(&out[(size_t)r * NDIM + c])       = v0;
            *reinterpret_cast<float2*>(&out[(size_t)(r + 8) * NDIM + c]) = v1;
        }
    }
}

// ========================= Launch =========================
extern "C" void kernel_launch(void* const* d_in, const int* in_sizes, int n_in,
                              void* d_out, int out_size) {
    const float* x    = (const float*)d_in[0];
    const int*   qw   = (const int*)d_in[1];
    const int*   qz   = (const int*)d_in[2];
    const float* sc   = (const float*)d_in[3];
    const float* bias = (const float*)d_in[4];
    float* out = (float*)d_out;

    // 1) merged prep: x->fp16  ||  dequant W->fp16
    prep_kernel<<<CONV_BLOCKS + DQ_BLOCKS, 256>>>(x, qw, qz, sc);

    // 2) fp16 GEMM (mma.sync), target 4 CTAs/SM (32 warps)
    cudaFuncSetAttribute(gemm_f16_kernel,
                         cudaFuncAttributeMaxDynamicSharedMemorySize, GEMM_SMEM);
    dim3 grid(MDIM / BM, NDIM / BN);   // m-major for L2 reuse of A within wave
    gemm_f16_kernel<<<grid, 256, GEMM_SMEM>>>(bias, out);
}

// round 13
// speedup vs baseline: 1.2235x; 1.2235x over previous
#include <cuda_runtime.h>
#include <cuda_fp16.h>
#include <cstdint>

// Shapes (fixed for this problem)
constexpr int MDIM = 4096;   // B*S
constexpr int KDIM = 4096;
constexpr int NDIM = 11008;
constexpr int GRP  = 128;

// -----------------------------------------------------------------------
// Scratch (allocation-free rule: __device__ globals)
//   g_A: [M][K] fp16 = fp16(x)
//   g_B: [N][K] fp16 = fp16((v - z) * scale)   (k-contiguous rows)
// -----------------------------------------------------------------------
__device__ __half g_A[(size_t)MDIM * KDIM];
__device__ __half g_B[(size_t)NDIM * KDIM];

// ========================= PTX helpers =========================
__device__ __forceinline__ uint32_t smem_u32(const void* p) {
    return (uint32_t)__cvta_generic_to_shared(p);
}
__device__ __forceinline__ void cp_async16(uint32_t smem, const void* gmem) {
    asm volatile("cp.async.cg.shared.global [%0], [%1], 16;\n"
                 :: "r"(smem), "l"(gmem));
}
__device__ __forceinline__ void cp_commit() {
    asm volatile("cp.async.commit_group;\n");
}
__device__ __forceinline__ void cp_wait0() {
    asm volatile("cp.async.wait_group 0;\n");
}
__device__ __forceinline__ void ldmatrix_x4(uint32_t& r0, uint32_t& r1,
                                            uint32_t& r2, uint32_t& r3,
                                            uint32_t addr) {
    asm volatile("ldmatrix.sync.aligned.m8n8.x4.shared.b16 {%0,%1,%2,%3}, [%4];\n"
                 : "=r"(r0), "=r"(r1), "=r"(r2), "=r"(r3) : "r"(addr));
}
__device__ __forceinline__ void mma_f16(float& c0, float& c1, float& c2, float& c3,
                                        uint32_t a0, uint32_t a1, uint32_t a2, uint32_t a3,
                                        uint32_t b0, uint32_t b1) {
    asm volatile("mma.sync.aligned.m16n8k16.row.col.f32.f16.f16.f32 "
                 "{%0,%1,%2,%3}, {%4,%5,%6,%7}, {%8,%9}, {%0,%1,%2,%3};\n"
                 : "+f"(c0), "+f"(c1), "+f"(c2), "+f"(c3)
                 : "r"(a0), "r"(a1), "r"(a2), "r"(a3), "r"(b0), "r"(b1));
}
// SW128-style swizzle on 128B rows: XOR bits [6:4] with bits [9:7]
__device__ __forceinline__ uint32_t swz(uint32_t o) {
    return o ^ ((o >> 3) & 0x70);
}

// ========================= Kernel 1: merged prep (R10, unchanged) =======
constexpr int CONV_BLOCKS = (MDIM * KDIM / 8) / 256;          // 8192
constexpr int DQ_NT = NDIM / 64;                               // 172
constexpr int DQ_KT = KDIM / 256;                              // 16
constexpr int DQ_BLOCKS = DQ_NT * DQ_KT;                       // 2752

constexpr int SH_STRIDE = 264;   // halfs per row (256 + 8 pad); chunk-swizzled

__global__ void prep_kernel(const float* __restrict__ x,
                            const int* __restrict__ qw,
                            const int* __restrict__ qz,
                            const float* __restrict__ sc) {
    const int tid = threadIdx.x;

    if (blockIdx.x < CONV_BLOCKS) {
        size_t i = (size_t)blockIdx.x * 256 + tid;
        const float4* x4 = reinterpret_cast<const float4*>(x);
        float4 a = x4[2 * i];
        float4 b = x4[2 * i + 1];
        __half2 h0 = __floats2half2_rn(a.x, a.y);
        __half2 h1 = __floats2half2_rn(a.z, a.w);
        __half2 h2 = __floats2half2_rn(b.x, b.y);
        __half2 h3 = __floats2half2_rn(b.z, b.w);
        uint4 o;
        o.x = *reinterpret_cast<uint32_t*>(&h0);
        o.y = *reinterpret_cast<uint32_t*>(&h1);
        o.z = *reinterpret_cast<uint32_t*>(&h2);
        o.w = *reinterpret_cast<uint32_t*>(&h3);
        reinterpret_cast<uint4*>(g_A)[i] = o;
        return;
    }

    __shared__ __half sh[64 * SH_STRIDE];
    __shared__ float  s_scale[2][64];
    __shared__ int    s_z[2][8];

    const int t  = blockIdx.x - CONV_BLOCKS;
    const int n0 = (t % DQ_NT) * 64;
    const int k0 = (t / DQ_NT) * 256;
    const int g0 = k0 / GRP;
    const int pw = NDIM / 8;

    if (tid < 128) {
        int g  = tid >> 6;
        int nl = tid & 63;
        s_scale[g][nl] = sc[(size_t)(g0 + g) * NDIM + n0 + nl];
    }
    if (tid < 16) {
        s_z[tid >> 3][tid & 7] = qz[(size_t)(g0 + (tid >> 3)) * pw + n0 / 8 + (tid & 7)];
    }
    __syncthreads();

    const int p  = tid & 7;
    const int kq = tid >> 3;
    const int grp = kq >> 4;
    const int zp = s_z[grp][p];

    const int shifts[8] = {0, 16, 4, 20, 8, 24, 12, 28};
    float sc8[8];
    int   z8[8];
#pragma unroll
    for (int j = 0; j < 8; j++) {
        sc8[j] = s_scale[grp][p * 8 + j];
        z8[j]  = (zp >> shifts[j]) & 0xF;
    }

    __half rows[8][8];
#pragma unroll
    for (int d = 0; d < 8; d++) {
        int packed = qw[(size_t)(k0 + kq * 8 + d) * pw + n0 / 8 + p];
#pragma unroll
        for (int j = 0; j < 8; j++) {
            int v = (packed >> shifts[j]) & 0xF;
            rows[j][d] = __float2half_rn((float)(v - z8[j]) * sc8[j]);
        }
    }

    const int chnk = kq ^ p;
#pragma unroll
    for (int j = 0; j < 8; j++) {
        int row = p * 8 + j;
        *reinterpret_cast<uint4*>(&sh[row * SH_STRIDE + chnk * 8]) =
            *reinterpret_cast<const uint4*>(&rows[j][0]);
    }
    __syncthreads();

#pragma unroll
    for (int it = 0; it < 8; it++) {
        int u   = tid + it * 256;
        int row = u >> 5;
        int c   = u & 31;
        int cs  = c ^ ((row >> 3) & 7);
        uint4 v = *reinterpret_cast<const uint4*>(&sh[row * SH_STRIDE + cs * 8]);
        *reinterpret_cast<uint4*>(&g_B[(size_t)(n0 + row) * KDIM + k0 + c * 8]) = v;
    }
}

// ========================= Kernel 2: fp16 GEMM (mma.sync) ================
// BM=128 BN=64 BK=64, 256 threads (4m x 2n warps, 32x32 warp tile),
// swizzled smem, 2-STAGE cp.async, 4 CTAs/SM (32 warps), one sync/iter.
constexpr int BM = 128, BN = 64, BK = 64;
constexpr int STAGES = 2;
constexpr int A_STAGE_BYTES = BM * BK * 2;     // 16384
constexpr int B_STAGE_BYTES = BN * BK * 2;     // 8192
constexpr int STAGE_BYTES = A_STAGE_BYTES + B_STAGE_BYTES;   // 24576
constexpr int GEMM_SMEM = STAGES * STAGE_BYTES;              // 49152

__global__ __launch_bounds__(256, 4)
void gemm_f16_kernel(const float* __restrict__ bias, float* __restrict__ out) {
    extern __shared__ __align__(128) uint8_t smem[];
    const uint32_t sbase = smem_u32(smem);

    const int tid  = threadIdx.x;
    const int lane = tid & 31;
    const int warp = tid >> 5;
    const int m0 = blockIdx.x * BM;       // m-major: wave covers all m tiles
    const int n0 = blockIdx.y * BN;
    const int wm = (warp & 3) * 32;       // 0/32/64/96
    const int wn = (warp >> 2) * 32;      // 0/32

    float acc[2][4][4];
#pragma unroll
    for (int a = 0; a < 2; a++)
#pragma unroll
        for (int b = 0; b < 4; b++)
#pragma unroll
            for (int c = 0; c < 4; c++) acc[a][b][c] = 0.0f;

    constexpr int T = KDIM / BK;  // 64

    // raw (pre-swizzle) per-lane ldmatrix offsets (R8-verified mappings)
    uint32_t araw[2], braw[2];
#pragma unroll
    for (int mt = 0; mt < 2; mt++)
        araw[mt] = (uint32_t)(wm + mt * 16 + (lane & 15)) * 128 +
                   ((uint32_t)(lane >> 4) << 4);
#pragma unroll
    for (int nt2 = 0; nt2 < 2; nt2++)
        braw[nt2] = (uint32_t)(wn + nt2 * 16 + ((lane >> 4) << 3) + (lane & 7)) * 128 +
                    (((uint32_t)(lane >> 3) & 1) << 4);

    // stage loader: A 128 rows x 8 chunks, B 64 rows x 8 chunks (16B each)
    auto load_stage = [&](int s, int bk) {
        uint32_t Ab = sbase + s * STAGE_BYTES;
        uint32_t Bb = Ab + A_STAGE_BYTES;
#pragma unroll
        for (int i = 0; i < 4; i++) {
            int id = tid + i * 256;
            int r = id >> 3, c = id & 7;
            cp_async16(Ab + swz((uint32_t)r * 128 + (uint32_t)c * 16),
                       &g_A[(size_t)(m0 + r) * KDIM + bk + c * 8]);
        }
#pragma unroll
        for (int i = 0; i < 2; i++) {
            int id = tid + i * 256;
            int r = id >> 3, c = id & 7;
            cp_async16(Bb + swz((uint32_t)r * 128 + (uint32_t)c * 16),
                       &g_B[(size_t)(n0 + r) * KDIM + bk + c * 8]);
        }
    };

    load_stage(0, 0);
    cp_commit();

    for (int t = 0; t < T; t++) {
        const int s = t & 1;
        cp_wait0();          // this thread's stage-t copies complete
        __syncthreads();     // publish ALL threads' stage t; compute t-1 retired

        if (t + 1 < T) {
            load_stage(s ^ 1, (t + 1) * BK);   // buffer consumed at iter t-1
            cp_commit();
        }

        const uint32_t stageA = sbase + s * STAGE_BYTES;
        const uint32_t stageB = stageA + A_STAGE_BYTES;

#pragma unroll
        for (int ks = 0; ks < 4; ks++) {
            uint32_t afr[2][4];
            uint32_t bfr[4][2];
#pragma unroll
            for (int mt = 0; mt < 2; mt++)
                ldmatrix_x4(afr[mt][0], afr[mt][1], afr[mt][2], afr[mt][3],
                            stageA + swz(araw[mt] + ks * 32));
#pragma unroll
            for (int nt2 = 0; nt2 < 2; nt2++)
                ldmatrix_x4(bfr[nt2 * 2][0], bfr[nt2 * 2][1],
                            bfr[nt2 * 2 + 1][0], bfr[nt2 * 2 + 1][1],
                            stageB + swz(braw[nt2] + ks * 32));
#pragma unroll
            for (int mt = 0; mt < 2; mt++)
#pragma unroll
                for (int nt = 0; nt < 4; nt++)
                    mma_f16(acc[mt][nt][0], acc[mt][nt][1], acc[mt][nt][2], acc[mt][nt][3],
                            afr[mt][0], afr[mt][1], afr[mt][2], afr[mt][3],
                            bfr[nt][0], bfr[nt][1]);
        }
    }

    // --- epilogue: += bias, fp32 stores ---
#pragma unroll
    for (int mt = 0; mt < 2; mt++) {
#pragma unroll
        for (int nt = 0; nt < 4; nt++) {
            int r = m0 + wm + mt * 16 + (lane >> 2);
            int c = n0 + wn + nt * 8 + (lane & 3) * 2;
            float2 bv = *reinterpret_cast<const float2*>(&bias[c]);
            float2 v0 = {acc[mt][nt][0] + bv.x, acc[mt][nt][1] + bv.y};
            float2 v1 = {acc[mt][nt][2] + bv.x, acc[mt][nt][3] + bv.y};
            *reinterpret_cast<float2*>(&out[(size_t)r * NDIM + c])       = v0;
            *reinterpret_cast<float2*>(&out[(size_t)(r + 8) * NDIM + c]) = v1;
        }
    }
}

// ========================= Launch =========================
extern "C" void kernel_launch(void* const* d_in, const int* in_sizes, int n_in,
                              void* d_out, int out_size) {
    const float* x    = (const float*)d_in[0];
    const int*   qw   = (const int*)d_in[1];
    const int*   qz   = (const int*)d_in[2];
    const float* sc   = (const float*)d_in[3];
    const float* bias = (const float*)d_in[4];
    float* out = (float*)d_out;

    // 1) merged prep: x->fp16  ||  dequant W->fp16
    prep_kernel<<<CONV_BLOCKS + DQ_BLOCKS, 256>>>(x, qw, qz, sc);

    // 2) fp16 GEMM (mma.sync), 2-stage, 4 CTAs/SM (32 warps)
    cudaFuncSetAttribute(gemm_f16_kernel,
                         cudaFuncAttributeMaxDynamicSharedMemorySize, GEMM_SMEM);
    dim3 grid(MDIM / BM, NDIM / BN);   // m-major for L2 reuse of A within wave
    gemm_f16_kernel<<<grid, 256, GEMM_SMEM>>>(bias, out);
}

// round 14
// speedup vs baseline: 1.3379x; 1.0935x over previous
#include <cuda_runtime.h>
#include <cuda_fp16.h>
#include <cstdint>

// Shapes (fixed for this problem)
constexpr int MDIM = 4096;   // B*S
constexpr int KDIM = 4096;
constexpr int NDIM = 11008;
constexpr int GRP  = 128;

// -----------------------------------------------------------------------
// Scratch (allocation-free rule: __device__ globals)
//   g_A: [M][K] fp16 = fp16(x)
//   g_B: [N][K] fp16 = fp16((v - z) * scale)   (k-contiguous rows)
// -----------------------------------------------------------------------
__device__ __half g_A[(size_t)MDIM * KDIM];
__device__ __half g_B[(size_t)NDIM * KDIM];

// ========================= PTX helpers =========================
__device__ __forceinline__ uint32_t smem_u32(const void* p) {
    return (uint32_t)__cvta_generic_to_shared(p);
}
__device__ __forceinline__ void cp_async16(uint32_t smem, const void* gmem) {
    asm volatile("cp.async.cg.shared.global [%0], [%1], 16;\n"
                 :: "r"(smem), "l"(gmem));
}
__device__ __forceinline__ void cp_commit() {
    asm volatile("cp.async.commit_group;\n");
}
__device__ __forceinline__ void cp_wait1() {
    asm volatile("cp.async.wait_group 1;\n");
}
__device__ __forceinline__ void ldmatrix_x4(uint32_t& r0, uint32_t& r1,
                                            uint32_t& r2, uint32_t& r3,
                                            uint32_t addr) {
    asm volatile("ldmatrix.sync.aligned.m8n8.x4.shared.b16 {%0,%1,%2,%3}, [%4];\n"
                 : "=r"(r0), "=r"(r1), "=r"(r2), "=r"(r3) : "r"(addr));
}
__device__ __forceinline__ void mma_f16(float& c0, float& c1, float& c2, float& c3,
                                        uint32_t a0, uint32_t a1, uint32_t a2, uint32_t a3,
                                        uint32_t b0, uint32_t b1) {
    asm volatile("mma.sync.aligned.m16n8k16.row.col.f32.f16.f16.f32 "
                 "{%0,%1,%2,%3}, {%4,%5,%6,%7}, {%8,%9}, {%0,%1,%2,%3};\n"
                 : "+f"(c0), "+f"(c1), "+f"(c2), "+f"(c3)
                 : "r"(a0), "r"(a1), "r"(a2), "r"(a3), "r"(b0), "r"(b1));
}
// SW128-style swizzle on 128B rows: XOR bits [6:4] with bits [9:7]
__device__ __forceinline__ uint32_t swz(uint32_t o) {
    return o ^ ((o >> 3) & 0x70);
}

// ========================= Kernel 1: merged prep ========================
// Blocks [0, DQ_BLOCKS)      : dequant W (heavy blocks FIRST for better tail)
// Blocks [DQ_BLOCKS, +CONV)  : x (fp32) -> g_A, 16 floats/thread
constexpr int DQ_NT = NDIM / 64;                               // 172
constexpr int DQ_KT = KDIM / 256;                              // 16
constexpr int DQ_BLOCKS = DQ_NT * DQ_KT;                       // 2752
constexpr int CONV_BLOCKS = (MDIM * KDIM / 16) / 256;          // 4096

constexpr int SH_STRIDE = 264;   // halfs per row (256 + 8 pad); chunk-swizzled

__global__ void prep_kernel(const float* __restrict__ x,
                            const int* __restrict__ qw,
                            const int* __restrict__ qz,
                            const float* __restrict__ sc) {
    const int tid = threadIdx.x;

    if (blockIdx.x >= DQ_BLOCKS) {
        // ---- conv x -> fp16, 16 floats per thread ----
        size_t i = ((size_t)(blockIdx.x - DQ_BLOCKS) * 256 + tid) * 2;
        const float4* x4 = reinterpret_cast<const float4*>(x);
#pragma unroll
        for (int h = 0; h < 2; h++) {
            float4 a = x4[2 * (i + h)];
            float4 b = x4[2 * (i + h) + 1];
            __half2 h0 = __floats2half2_rn(a.x, a.y);
            __half2 h1 = __floats2half2_rn(a.z, a.w);
            __half2 h2 = __floats2half2_rn(b.x, b.y);
            __half2 h3 = __floats2half2_rn(b.z, b.w);
            uint4 o;
            o.x = *reinterpret_cast<uint32_t*>(&h0);
            o.y = *reinterpret_cast<uint32_t*>(&h1);
            o.z = *reinterpret_cast<uint32_t*>(&h2);
            o.w = *reinterpret_cast<uint32_t*>(&h3);
            reinterpret_cast<uint4*>(g_A)[i + h] = o;
        }
        return;
    }

    // ---- dequant W: tile 256 k x 64 n (two quant groups along k) ----
    __shared__ __half sh[64 * SH_STRIDE];
    __shared__ float  s_scale[2][64];
    __shared__ int    s_z[2][8];

    const int t  = blockIdx.x;
    const int n0 = (t % DQ_NT) * 64;
    const int k0 = (t / DQ_NT) * 256;
    const int g0 = k0 / GRP;
    const int pw = NDIM / 8;

    if (tid < 128) {
        int g  = tid >> 6;
        int nl = tid & 63;
        s_scale[g][nl] = sc[(size_t)(g0 + g) * NDIM + n0 + nl];
    }
    if (tid < 16) {
        s_z[tid >> 3][tid & 7] = qz[(size_t)(g0 + (tid >> 3)) * pw + n0 / 8 + (tid & 7)];
    }
    __syncthreads();

    const int p  = tid & 7;
    const int kq = tid >> 3;
    const int grp = kq >> 4;
    const int zp = s_z[grp][p];

    const int shifts[8] = {0, 16, 4, 20, 8, 24, 12, 28};
    float sc8[8];
    int   z8[8];
#pragma unroll
    for (int j = 0; j < 8; j++) {
        sc8[j] = s_scale[grp][p * 8 + j];
        z8[j]  = (zp >> shifts[j]) & 0xF;
    }

    __half rows[8][8];
#pragma unroll
    for (int d = 0; d < 8; d++) {
        int packed = qw[(size_t)(k0 + kq * 8 + d) * pw + n0 / 8 + p];
#pragma unroll
        for (int j = 0; j < 8; j++) {
            int v = (packed >> shifts[j]) & 0xF;
            rows[j][d] = __float2half_rn((float)(v - z8[j]) * sc8[j]);
        }
    }

    const int chnk = kq ^ p;
#pragma unroll
    for (int j = 0; j < 8; j++) {
        int row = p * 8 + j;
        *reinterpret_cast<uint4*>(&sh[row * SH_STRIDE + chnk * 8]) =
            *reinterpret_cast<const uint4*>(&rows[j][0]);
    }
    __syncthreads();

#pragma unroll
    for (int it = 0; it < 8; it++) {
        int u   = tid + it * 256;
        int row = u >> 5;
        int c   = u & 31;
        int cs  = c ^ ((row >> 3) & 7);
        uint4 v = *reinterpret_cast<const uint4*>(&sh[row * SH_STRIDE + cs * 8]);
        *reinterpret_cast<uint4*>(&g_B[(size_t)(n0 + row) * KDIM + k0 + c * 8]) = v;
    }
}

// ========================= Kernel 2: fp16 GEMM (mma.sync) ================
// R8/R10 winner, verbatim config: BM=128 BN=64 BK=64, 8 warps (4m x 2n),
// warp tile 32x32, swizzled smem, 3-stage cp.async, 3 CTAs/SM.
// tensor 75.3% = smem-crossbar cap (0.172 B/MAC): measured == modeled.
constexpr int BM = 128, BN = 64, BK = 64;
constexpr int STAGES = 3;
constexpr int A_STAGE_BYTES = BM * BK * 2;     // 16384
constexpr int B_STAGE_BYTES = BN * BK * 2;     // 8192
constexpr int STAGE_BYTES = A_STAGE_BYTES + B_STAGE_BYTES;   // 24576
constexpr int GEMM_SMEM = STAGES * STAGE_BYTES;              // 73728

__global__ __launch_bounds__(256, 3)
void gemm_f16_kernel(const float* __restrict__ bias, float* __restrict__ out) {
    extern __shared__ __align__(128) uint8_t smem[];
    const uint32_t sbase = smem_u32(smem);

    const int tid  = threadIdx.x;
    const int lane = tid & 31;
    const int warp = tid >> 5;
    const int m0 = blockIdx.x * BM;       // m-major: wave covers all m tiles
    const int n0 = blockIdx.y * BN;
    const int wm = (warp & 3) * 32;       // 0/32/64/96
    const int wn = (warp >> 2) * 32;      // 0/32

    float acc[2][4][4];
#pragma unroll
    for (int a = 0; a < 2; a++)
#pragma unroll
        for (int b = 0; b < 4; b++)
#pragma unroll
            for (int c = 0; c < 4; c++) acc[a][b][c] = 0.0f;

    constexpr int T = KDIM / BK;  // 64

    uint32_t araw[2], braw[2];
#pragma unroll
    for (int mt = 0; mt < 2; mt++)
        araw[mt] = (uint32_t)(wm + mt * 16 + (lane & 15)) * 128 +
                   ((uint32_t)(lane >> 4) << 4);
#pragma unroll
    for (int nt2 = 0; nt2 < 2; nt2++)
        braw[nt2] = (uint32_t)(wn + nt2 * 16 + ((lane >> 4) << 3) + (lane & 7)) * 128 +
                    (((uint32_t)(lane >> 3) & 1) << 4);

    auto load_stage = [&](int s, int bk) {
        uint32_t Ab = sbase + s * STAGE_BYTES;
        uint32_t Bb = Ab + A_STAGE_BYTES;
#pragma unroll
        for (int i = 0; i < 4; i++) {
            int id = tid + i * 256;
            int r = id >> 3, c = id & 7;
            cp_async16(Ab + swz((uint32_t)r * 128 + (uint32_t)c * 16),
                       &g_A[(size_t)(m0 + r) * KDIM + bk + c * 8]);
        }
#pragma unroll
        for (int i = 0; i < 2; i++) {
            int id = tid + i * 256;
            int r = id >> 3, c = id & 7;
            cp_async16(Bb + swz((uint32_t)r * 128 + (uint32_t)c * 16),
                       &g_B[(size_t)(n0 + r) * KDIM + bk + c * 8]);
        }
    };

    load_stage(0, 0);  cp_commit();
    load_stage(1, BK); cp_commit();

    int s = 0;
#pragma unroll 3
    for (int t = 0; t < T; t++) {
        cp_wait1();
        __syncthreads();

        if (t + 2 < T) {
            int ns = s + 2;
            if (ns >= STAGES) ns -= STAGES;
            load_stage(ns, (t + 2) * BK);
        }
        cp_commit();

        const uint32_t stageA = sbase + s * STAGE_BYTES;
        const uint32_t stageB = stageA + A_STAGE_BYTES;

#pragma unroll
        for (int ks = 0; ks < 4; ks++) {
            uint32_t afr[2][4];
            uint32_t bfr[4][2];
#pragma unroll
            for (int mt = 0; mt < 2; mt++)
                ldmatrix_x4(afr[mt][0], afr[mt][1], afr[mt][2], afr[mt][3],
                            stageA + swz(araw[mt] + ks * 32));
#pragma unroll
            for (int nt2 = 0; nt2 < 2; nt2++)
                ldmatrix_x4(bfr[nt2 * 2][0], bfr[nt2 * 2][1],
                            bfr[nt2 * 2 + 1][0], bfr[nt2 * 2 + 1][1],
                            stageB + swz(braw[nt2] + ks * 32));
#pragma unroll
            for (int mt = 0; mt < 2; mt++)
#pragma unroll
                for (int nt = 0; nt < 4; nt++)
                    mma_f16(acc[mt][nt][0], acc[mt][nt][1], acc[mt][nt][2], acc[mt][nt][3],
                            afr[mt][0], afr[mt][1], afr[mt][2], afr[mt][3],
                            bfr[nt][0], bfr[nt][1]);
        }
        if (++s == STAGES) s = 0;
    }

    // --- epilogue: += bias, fp32 stores ---
#pragma unroll
    for (int mt = 0; mt < 2; mt++) {
#pragma unroll
        for (int nt = 0; nt < 4; nt++) {
            int r = m0 + wm + mt * 16 + (lane >> 2);
            int c = n0 + wn + nt * 8 + (lane & 3) * 2;
            float2 bv = *reinterpret_cast<const float2*>(&bias[c]);
            float2 v0 = {acc[mt][nt][0] + bv.x, acc[mt][nt][1] + bv.y};
            float2 v1 = {acc[mt][nt][2] + bv.x, acc[mt][nt][3] + bv.y};
            *reinterpret_cast<float2*>(&out[(size_t)r * NDIM + c])       = v0;
            *reinterpret_cast<float2*>(&out[(size_t)(r + 8) * NDIM + c]) = v1;
        }
    }
}

// ========================= Launch =========================
extern "C" void kernel_launch(void* const* d_in, const int* in_sizes, int n_in,
                              void* d_out, int out_size) {
    const float* x    = (const float*)d_in[0];
    const int*   qw   = (const int*)d_in[1];
    const int*   qz   = (const int*)d_in[2];
    const float* sc   = (const float*)d_in[3];
    const float* bias = (const float*)d_in[4];
    float* out = (float*)d_out;

    // 1) merged prep: dequant W (heavy, first) || x->fp16 (light, tail)
    prep_kernel<<<DQ_BLOCKS + CONV_BLOCKS, 256>>>(x, qw, qz, sc);

    // 2) fp16 GEMM (mma.sync), 3-stage, 3 CTAs/SM  [R8 winner]
    cudaFuncSetAttribute(gemm_f16_kernel,
                         cudaFuncAttributeMaxDynamicSharedMemorySize, GEMM_SMEM);
    dim3 grid(MDIM / BM, NDIM / BN);   // m-major for L2 reuse of A within wave
    gemm_f16_kernel<<<grid, 256, GEMM_SMEM>>>(bias, out);
}

// round 15
// speedup vs baseline: 1.3970x; 1.0442x over previous
#include <cuda_runtime.h>
#include <cuda_fp16.h>
#include <cstdint>

// Shapes (fixed for this problem)
constexpr int MDIM = 4096;   // B*S
constexpr int KDIM = 4096;
constexpr int NDIM = 11008;
constexpr int GRP  = 128;

// -----------------------------------------------------------------------
// Scratch (allocation-free rule: __device__ globals)
//   g_A: [M][K] fp16 = fp16(x)
//   g_B: [N][K] fp16 = fp16((v - z) * scale)   (k-contiguous rows)
// -----------------------------------------------------------------------
__device__ __half g_A[(size_t)MDIM * KDIM];
__device__ __half g_B[(size_t)NDIM * KDIM];

// ========================= PTX helpers =========================
__device__ __forceinline__ uint32_t smem_u32(const void* p) {
    return (uint32_t)__cvta_generic_to_shared(p);
}
__device__ __forceinline__ void cp_async16(uint32_t smem, const void* gmem) {
    asm volatile("cp.async.cg.shared.global [%0], [%1], 16;\n"
                 :: "r"(smem), "l"(gmem));
}
__device__ __forceinline__ void cp_commit() {
    asm volatile("cp.async.commit_group;\n");
}
__device__ __forceinline__ void cp_wait1() {
    asm volatile("cp.async.wait_group 1;\n");
}
__device__ __forceinline__ void ldmatrix_x4(uint32_t& r0, uint32_t& r1,
                                            uint32_t& r2, uint32_t& r3,
                                            uint32_t addr) {
    asm volatile("ldmatrix.sync.aligned.m8n8.x4.shared.b16 {%0,%1,%2,%3}, [%4];\n"
                 : "=r"(r0), "=r"(r1), "=r"(r2), "=r"(r3) : "r"(addr));
}
__device__ __forceinline__ void mma_f16(float& c0, float& c1, float& c2, float& c3,
                                        uint32_t a0, uint32_t a1, uint32_t a2, uint32_t a3,
                                        uint32_t b0, uint32_t b1) {
    asm volatile("mma.sync.aligned.m16n8k16.row.col.f32.f16.f16.f32 "
                 "{%0,%1,%2,%3}, {%4,%5,%6,%7}, {%8,%9}, {%0,%1,%2,%3};\n"
                 : "+f"(c0), "+f"(c1), "+f"(c2), "+f"(c3)
                 : "r"(a0), "r"(a1), "r"(a2), "r"(a3), "r"(b0), "r"(b1));
}
// SW128-style swizzle on 128B rows: XOR bits [6:4] with bits [9:7]
__device__ __forceinline__ uint32_t swz(uint32_t o) {
    return o ^ ((o >> 3) & 0x70);
}

// ========================= Kernel 1: merged prep ========================
// Blocks [0, DQ_BLOCKS)          : dequant W (heavy blocks FIRST: LPT order)
// Blocks [DQ_BLOCKS, +CONV)      : x (fp32) -> g_A, 8 floats/thread (R10 path)
constexpr int DQ_NT = NDIM / 64;                               // 172
constexpr int DQ_KT = KDIM / 256;                              // 16
constexpr int DQ_BLOCKS = DQ_NT * DQ_KT;                       // 2752
constexpr int CONV_BLOCKS = (MDIM * KDIM / 8) / 256;           // 8192

constexpr int SH_STRIDE = 264;   // halfs per row (256 + 8 pad); chunk-swizzled

__global__ void prep_kernel(const float* __restrict__ x,
                            const int* __restrict__ qw,
                            const int* __restrict__ qz,
                            const float* __restrict__ sc) {
    const int tid = threadIdx.x;

    if (blockIdx.x >= DQ_BLOCKS) {
        // ---- conv x -> fp16, 8 floats per thread (R10-verified path) ----
        size_t i = (size_t)(blockIdx.x - DQ_BLOCKS) * 256 + tid;
        const float4* x4 = reinterpret_cast<const float4*>(x);
        float4 a = x4[2 * i];
        float4 b = x4[2 * i + 1];
        __half2 h0 = __floats2half2_rn(a.x, a.y);
        __half2 h1 = __floats2half2_rn(a.z, a.w);
        __half2 h2 = __floats2half2_rn(b.x, b.y);
        __half2 h3 = __floats2half2_rn(b.z, b.w);
        uint4 o;
        o.x = *reinterpret_cast<uint32_t*>(&h0);
        o.y = *reinterpret_cast<uint32_t*>(&h1);
        o.z = *reinterpret_cast<uint32_t*>(&h2);
        o.w = *reinterpret_cast<uint32_t*>(&h3);
        reinterpret_cast<uint4*>(g_A)[i] = o;
        return;
    }

    // ---- dequant W: tile 256 k x 64 n (two quant groups along k) ----
    __shared__ __half sh[64 * SH_STRIDE];
    __shared__ float  s_scale[2][64];
    __shared__ int    s_z[2][8];

    const int t  = blockIdx.x;
    const int n0 = (t % DQ_NT) * 64;
    const int k0 = (t / DQ_NT) * 256;
    const int g0 = k0 / GRP;
    const int pw = NDIM / 8;

    if (tid < 128) {
        int g  = tid >> 6;
        int nl = tid & 63;
        s_scale[g][nl] = sc[(size_t)(g0 + g) * NDIM + n0 + nl];
    }
    if (tid < 16) {
        s_z[tid >> 3][tid & 7] = qz[(size_t)(g0 + (tid >> 3)) * pw + n0 / 8 + (tid & 7)];
    }
    __syncthreads();

    const int p  = tid & 7;
    const int kq = tid >> 3;
    const int grp = kq >> 4;
    const int zp = s_z[grp][p];

    const int shifts[8] = {0, 16, 4, 20, 8, 24, 12, 28};
    float sc8[8];
    int   z8[8];
#pragma unroll
    for (int j = 0; j < 8; j++) {
        sc8[j] = s_scale[grp][p * 8 + j];
        z8[j]  = (zp >> shifts[j]) & 0xF;
    }

    __half rows[8][8];
#pragma unroll
    for (int d = 0; d < 8; d++) {
        int packed = qw[(size_t)(k0 + kq * 8 + d) * pw + n0 / 8 + p];
#pragma unroll
        for (int j = 0; j < 8; j++) {
            int v = (packed >> shifts[j]) & 0xF;
            rows[j][d] = __float2half_rn((float)(v - z8[j]) * sc8[j]);
        }
    }

    const int chnk = kq ^ p;
#pragma unroll
    for (int j = 0; j < 8; j++) {
        int row = p * 8 + j;
        *reinterpret_cast<uint4*>(&sh[row * SH_STRIDE + chnk * 8]) =
            *reinterpret_cast<const uint4*>(&rows[j][0]);
    }
    __syncthreads();

#pragma unroll
    for (int it = 0; it < 8; it++) {
        int u   = tid + it * 256;
        int row = u >> 5;
        int c   = u & 31;
        int cs  = c ^ ((row >> 3) & 7);
        uint4 v = *reinterpret_cast<const uint4*>(&sh[row * SH_STRIDE + cs * 8]);
        *reinterpret_cast<uint4*>(&g_B[(size_t)(n0 + row) * KDIM + k0 + c * 8]) = v;
    }
}

// ========================= Kernel 2: fp16 GEMM (mma.sync) ================
// R10 winner VERBATIM: BM=128 BN=64 BK=64, 8 warps (4m x 2n), 32x32 warp
// tile, swizzled smem, 3-stage cp.async, 3 CTAs/SM, NO unroll pragma.
// tensor 75.3% = smem-crossbar cap (0.172 B/MAC): measured == modeled.
constexpr int BM = 128, BN = 64, BK = 64;
constexpr int STAGES = 3;
constexpr int A_STAGE_BYTES = BM * BK * 2;     // 16384
constexpr int B_STAGE_BYTES = BN * BK * 2;     // 8192
constexpr int STAGE_BYTES = A_STAGE_BYTES + B_STAGE_BYTES;   // 24576
constexpr int GEMM_SMEM = STAGES * STAGE_BYTES;              // 73728

__global__ __launch_bounds__(256, 3)
void gemm_f16_kernel(const float* __restrict__ bias, float* __restrict__ out) {
    extern __shared__ __align__(128) uint8_t smem[];
    const uint32_t sbase = smem_u32(smem);

    const int tid  = threadIdx.x;
    const int lane = tid & 31;
    const int warp = tid >> 5;
    const int m0 = blockIdx.x * BM;       // m-major: wave covers all m tiles
    const int n0 = blockIdx.y * BN;
    const int wm = (warp & 3) * 32;       // 0/32/64/96
    const int wn = (warp >> 2) * 32;      // 0/32

    float acc[2][4][4];
#pragma unroll
    for (int a = 0; a < 2; a++)
#pragma unroll
        for (int b = 0; b < 4; b++)
#pragma unroll
            for (int c = 0; c < 4; c++) acc[a][b][c] = 0.0f;

    constexpr int T = KDIM / BK;  // 64

    uint32_t araw[2], braw[2];
#pragma unroll
    for (int mt = 0; mt < 2; mt++)
        araw[mt] = (uint32_t)(wm + mt * 16 + (lane & 15)) * 128 +
                   ((uint32_t)(lane >> 4) << 4);
#pragma unroll
    for (int nt2 = 0; nt2 < 2; nt2++)
        braw[nt2] = (uint32_t)(wn + nt2 * 16 + ((lane >> 4) << 3) + (lane & 7)) * 128 +
                    (((uint32_t)(lane >> 3) & 1) << 4);

    auto load_stage = [&](int s, int bk) {
        uint32_t Ab = sbase + s * STAGE_BYTES;
        uint32_t Bb = Ab + A_STAGE_BYTES;
#pragma unroll
        for (int i = 0; i < 4; i++) {
            int id = tid + i * 256;
            int r = id >> 3, c = id & 7;
            cp_async16(Ab + swz((uint32_t)r * 128 + (uint32_t)c * 16),
                       &g_A[(size_t)(m0 + r) * KDIM + bk + c * 8]);
        }
#pragma unroll
        for (int i = 0; i < 2; i++) {
            int id = tid + i * 256;
            int r = id >> 3, c = id & 7;
            cp_async16(Bb + swz((uint32_t)r * 128 + (uint32_t)c * 16),
                       &g_B[(size_t)(n0 + r) * KDIM + bk + c * 8]);
        }
    };

    load_stage(0, 0);  cp_commit();
    load_stage(1, BK); cp_commit();

    int s = 0;
    for (int t = 0; t < T; t++) {
        cp_wait1();
        __syncthreads();

        if (t + 2 < T) {
            int ns = s + 2;
            if (ns >= STAGES) ns -= STAGES;
            load_stage(ns, (t + 2) * BK);
        }
        cp_commit();

        const uint32_t stageA = sbase + s * STAGE_BYTES;
        const uint32_t stageB = stageA + A_STAGE_BYTES;

#pragma unroll
        for (int ks = 0; ks < 4; ks++) {
            uint32_t afr[2][4];
            uint32_t bfr[4][2];
#pragma unroll
            for (int mt = 0; mt < 2; mt++)
                ldmatrix_x4(afr[mt][0], afr[mt][1], afr[mt][2], afr[mt][3],
                            stageA + swz(araw[mt] + ks * 32));
#pragma unroll
            for (int nt2 = 0; nt2 < 2; nt2++)
                ldmatrix_x4(bfr[nt2 * 2][0], bfr[nt2 * 2][1],
                            bfr[nt2 * 2 + 1][0], bfr[nt2 * 2 + 1][1],
                            stageB + swz(braw[nt2] + ks * 32));
#pragma unroll
            for (int mt = 0; mt < 2; mt++)
#pragma unroll
                for (int nt = 0; nt < 4; nt++)
                    mma_f16(acc[mt][nt][0], acc[mt][nt][1], acc[mt][nt][2], acc[mt][nt][3],
                            afr[mt][0], afr[mt][1], afr[mt][2], afr[mt][3],
                            bfr[nt][0], bfr[nt][1]);
        }
        if (++s == STAGES) s = 0;
    }

    // --- epilogue: += bias, fp32 stores ---
#pragma unroll
    for (int mt = 0; mt < 2; mt++) {
#pragma unroll
        for (int nt = 0; nt < 4; nt++) {
            int r = m0 + wm + mt * 16 + (lane >> 2);
            int c = n0 + wn + nt * 8 + (lane & 3) * 2;
            float2 bv = *reinterpret_cast<const float2*>(&bias[c]);
            float2 v0 = {acc[mt][nt][0] + bv.x, acc[mt][nt][1] + bv.y};
            float2 v1 = {acc[mt][nt][2] + bv.x, acc[mt][nt][3] + bv.y};
            *reinterpret_cast<float2*>(&out[(size_t)r * NDIM + c])       = v0;
            *reinterpret_cast<float2*>(&out[(size_t)(r + 8) * NDIM + c]) = v1;
        }
    }
}

// ========================= Launch =========================
extern "C" void kernel_launch(void* const* d_in, const int* in_sizes, int n_in,
                              void* d_out, int out_size) {
    const float* x    = (const float*)d_in[0];
    const int*   qw   = (const int*)d_in[1];
    const int*   qz   = (const int*)d_in[2];
    const float* sc   = (const float*)d_in[3];
    const float* bias = (const float*)d_in[4];
    float* out = (float*)d_out;

    // 1) merged prep: dequant W (heavy, first — LPT) || x->fp16 (light tail)
    prep_kernel<<<DQ_BLOCKS + CONV_BLOCKS, 256>>>(x, qw, qz, sc);

    // 2) fp16 GEMM (mma.sync), 3-stage, 3 CTAs/SM  [R10 winner verbatim]
    cudaFuncSetAttribute(gemm_f16_kernel,
                         cudaFuncAttributeMaxDynamicSharedMemorySize, GEMM_SMEM);
    dim3 grid(MDIM / BM, NDIM / BN);   // m-major for L2 reuse of A within wave
    gemm_f16_kernel<<<grid, 256, GEMM_SMEM>>>(bias, out);
}

// round 16
// speedup vs baseline: 1.4027x; 1.0040x over previous
#include <cuda_runtime.h>
#include <cuda_fp16.h>
#include <cstdint>

// Shapes (fixed for this problem)
constexpr int MDIM = 4096;   // B*S
constexpr int KDIM = 4096;
constexpr int NDIM = 11008;
constexpr int GRP  = 128;

// -----------------------------------------------------------------------
// Scratch (allocation-free rule: __device__ globals)
//   g_A: [M][K] fp16 = fp16(x)
//   g_B: [N][K] fp16 = fp16((v - z) * scale)   (k-contiguous rows)
// Single-fp16 GEMM error model: rel_err ~ 2.7e-4 (measured, stable).
// -----------------------------------------------------------------------
__device__ __half g_A[(size_t)MDIM * KDIM];
__device__ __half g_B[(size_t)NDIM * KDIM];

// ========================= PTX helpers =========================
__device__ __forceinline__ uint32_t smem_u32(const void* p) {
    return (uint32_t)__cvta_generic_to_shared(p);
}
__device__ __forceinline__ void cp_async16(uint32_t smem, const void* gmem) {
    asm volatile("cp.async.cg.shared.global [%0], [%1], 16;\n"
                 :: "r"(smem), "l"(gmem));
}
__device__ __forceinline__ void cp_commit() {
    asm volatile("cp.async.commit_group;\n");
}
__device__ __forceinline__ void cp_wait1() {
    asm volatile("cp.async.wait_group 1;\n");
}
__device__ __forceinline__ void ldmatrix_x4(uint32_t& r0, uint32_t& r1,
                                            uint32_t& r2, uint32_t& r3,
                                            uint32_t addr) {
    asm volatile("ldmatrix.sync.aligned.m8n8.x4.shared.b16 {%0,%1,%2,%3}, [%4];\n"
                 : "=r"(r0), "=r"(r1), "=r"(r2), "=r"(r3) : "r"(addr));
}
__device__ __forceinline__ void mma_f16(float& c0, float& c1, float& c2, float& c3,
                                        uint32_t a0, uint32_t a1, uint32_t a2, uint32_t a3,
                                        uint32_t b0, uint32_t b1) {
    asm volatile("mma.sync.aligned.m16n8k16.row.col.f32.f16.f16.f32 "
                 "{%0,%1,%2,%3}, {%4,%5,%6,%7}, {%8,%9}, {%0,%1,%2,%3};\n"
                 : "+f"(c0), "+f"(c1), "+f"(c2), "+f"(c3)
                 : "r"(a0), "r"(a1), "r"(a2), "r"(a3), "r"(b0), "r"(b1));
}
// SW128-style swizzle on 128B rows: XOR bits [6:4] with bits [9:7]
__device__ __forceinline__ uint32_t swz(uint32_t o) {
    return o ^ ((o >> 3) & 0x70);
}

// ========================= Kernel 1: merged prep (R10 order) ============
// Blocks [0, CONV_BLOCKS)          : x (fp32) -> g_A (fp16)  [DRAM-bound]
// Blocks [CONV_BLOCKS, +DQ_BLOCKS) : dequant W (256k x 64n)  [L2/compute]
// conv-first measured best: dequant compute overlaps conv's DRAM tail.
constexpr int CONV_BLOCKS = (MDIM * KDIM / 8) / 256;          // 8192
constexpr int DQ_NT = NDIM / 64;                               // 172
constexpr int DQ_KT = KDIM / 256;                              // 16
constexpr int DQ_BLOCKS = DQ_NT * DQ_KT;                       // 2752

constexpr int SH_STRIDE = 264;   // halfs per row (256 + 8 pad); chunk-swizzled

__global__ void prep_kernel(const float* __restrict__ x,
                            const int* __restrict__ qw,
                            const int* __restrict__ qz,
                            const float* __restrict__ sc) {
    const int tid = threadIdx.x;

    if (blockIdx.x < CONV_BLOCKS) {
        // ---- conv x -> fp16, 8 floats per thread ----
        size_t i = (size_t)blockIdx.x * 256 + tid;
        const float4* x4 = reinterpret_cast<const float4*>(x);
        float4 a = x4[2 * i];
        float4 b = x4[2 * i + 1];
        __half2 h0 = __floats2half2_rn(a.x, a.y);
        __half2 h1 = __floats2half2_rn(a.z, a.w);
        __half2 h2 = __floats2half2_rn(b.x, b.y);
        __half2 h3 = __floats2half2_rn(b.z, b.w);
        uint4 o;
        o.x = *reinterpret_cast<uint32_t*>(&h0);
        o.y = *reinterpret_cast<uint32_t*>(&h1);
        o.z = *reinterpret_cast<uint32_t*>(&h2);
        o.w = *reinterpret_cast<uint32_t*>(&h3);
        reinterpret_cast<uint4*>(g_A)[i] = o;
        return;
    }

    // ---- dequant W: tile 256 k x 64 n (two quant groups along k) ----
    // Per thread: packed col p (8 n's) x 8 consecutive k's -> 8x8 register
    // block -> 8 conflict-free STS.128 (chunk XOR swizzle).
    __shared__ __half sh[64 * SH_STRIDE];
    __shared__ float  s_scale[2][64];
    __shared__ int    s_z[2][8];

    const int t  = blockIdx.x - CONV_BLOCKS;
    const int n0 = (t % DQ_NT) * 64;
    const int k0 = (t / DQ_NT) * 256;
    const int g0 = k0 / GRP;
    const int pw = NDIM / 8;

    if (tid < 128) {
        int g  = tid >> 6;
        int nl = tid & 63;
        s_scale[g][nl] = sc[(size_t)(g0 + g) * NDIM + n0 + nl];
    }
    if (tid < 16) {
        s_z[tid >> 3][tid & 7] = qz[(size_t)(g0 + (tid >> 3)) * pw + n0 / 8 + (tid & 7)];
    }
    __syncthreads();

    const int p  = tid & 7;
    const int kq = tid >> 3;
    const int grp = kq >> 4;
    const int zp = s_z[grp][p];

    const int shifts[8] = {0, 16, 4, 20, 8, 24, 12, 28};
    float sc8[8];
    int   z8[8];
#pragma unroll
    for (int j = 0; j < 8; j++) {
        sc8[j] = s_scale[grp][p * 8 + j];
        z8[j]  = (zp >> shifts[j]) & 0xF;
    }

    __half rows[8][8];
#pragma unroll
    for (int d = 0; d < 8; d++) {
        int packed = qw[(size_t)(k0 + kq * 8 + d) * pw + n0 / 8 + p];
#pragma unroll
        for (int j = 0; j < 8; j++) {
            int v = (packed >> shifts[j]) & 0xF;
            rows[j][d] = __float2half_rn((float)(v - z8[j]) * sc8[j]);
        }
    }

    const int chnk = kq ^ p;
#pragma unroll
    for (int j = 0; j < 8; j++) {
        int row = p * 8 + j;
        *reinterpret_cast<uint4*>(&sh[row * SH_STRIDE + chnk * 8]) =
            *reinterpret_cast<const uint4*>(&rows[j][0]);
    }
    __syncthreads();

#pragma unroll
    for (int it = 0; it < 8; it++) {
        int u   = tid + it * 256;
        int row = u >> 5;
        int c   = u & 31;
        int cs  = c ^ ((row >> 3) & 7);
        uint4 v = *reinterpret_cast<const uint4*>(&sh[row * SH_STRIDE + cs * 8]);
        *reinterpret_cast<uint4*>(&g_B[(size_t)(n0 + row) * KDIM + k0 + c * 8]) = v;
    }
}

// ========================= Kernel 2: fp16 GEMM (mma.sync) ================
// R10 winner VERBATIM: BM=128 BN=64 BK=64, 8 warps (4m x 2n), 32x32 warp
// tile, swizzled smem, 3-stage cp.async, 3 CTAs/SM, no unroll pragma.
// tensor 75.3-75.4% = smem-crossbar cap at 0.172 B/MAC (measured == model).
constexpr int BM = 128, BN = 64, BK = 64;
constexpr int STAGES = 3;
constexpr int A_STAGE_BYTES = BM * BK * 2;     // 16384
constexpr int B_STAGE_BYTES = BN * BK * 2;     // 8192
constexpr int STAGE_BYTES = A_STAGE_BYTES + B_STAGE_BYTES;   // 24576
constexpr int GEMM_SMEM = STAGES * STAGE_BYTES;              // 73728

__global__ __launch_bounds__(256, 3)
void gemm_f16_kernel(const float* __restrict__ bias, float* __restrict__ out) {
    extern __shared__ __align__(128) uint8_t smem[];
    const uint32_t sbase = smem_u32(smem);

    const int tid  = threadIdx.x;
    const int lane = tid & 31;
    const int warp = tid >> 5;
    const int m0 = blockIdx.x * BM;       // m-major: wave covers all m tiles
    const int n0 = blockIdx.y * BN;
    const int wm = (warp & 3) * 32;       // 0/32/64/96
    const int wn = (warp >> 2) * 32;      // 0/32

    float acc[2][4][4];
#pragma unroll
    for (int a = 0; a < 2; a++)
#pragma unroll
        for (int b = 0; b < 4; b++)
#pragma unroll
            for (int c = 0; c < 4; c++) acc[a][b][c] = 0.0f;

    constexpr int T = KDIM / BK;  // 64

    // raw (pre-swizzle) per-lane ldmatrix offsets; swz applied after +ks*32
    uint32_t araw[2], braw[2];
#pragma unroll
    for (int mt = 0; mt < 2; mt++)
        araw[mt] = (uint32_t)(wm + mt * 16 + (lane & 15)) * 128 +
                   ((uint32_t)(lane >> 4) << 4);
#pragma unroll
    for (int nt2 = 0; nt2 < 2; nt2++)
        braw[nt2] = (uint32_t)(wn + nt2 * 16 + ((lane >> 4) << 3) + (lane & 7)) * 128 +
                    (((uint32_t)(lane >> 3) & 1) << 4);

    auto load_stage = [&](int s, int bk) {
        uint32_t Ab = sbase + s * STAGE_BYTES;
        uint32_t Bb = Ab + A_STAGE_BYTES;
#pragma unroll
        for (int i = 0; i < 4; i++) {
            int id = tid + i * 256;
            int r = id >> 3, c = id & 7;
            cp_async16(Ab + swz((uint32_t)r * 128 + (uint32_t)c * 16),
                       &g_A[(size_t)(m0 + r) * KDIM + bk + c * 8]);
        }
#pragma unroll
        for (int i = 0; i < 2; i++) {
            int id = tid + i * 256;
            int r = id >> 3, c = id & 7;
            cp_async16(Bb + swz((uint32_t)r * 128 + (uint32_t)c * 16),
                       &g_B[(size_t)(n0 + r) * KDIM + bk + c * 8]);
        }
    };

    load_stage(0, 0);  cp_commit();
    load_stage(1, BK); cp_commit();

    int s = 0;
    for (int t = 0; t < T; t++) {
        cp_wait1();          // stage t resident
        __syncthreads();     // overwritten slot provably consumed

        if (t + 2 < T) {
            int ns = s + 2;
            if (ns >= STAGES) ns -= STAGES;
            load_stage(ns, (t + 2) * BK);
        }
        cp_commit();

        const uint32_t stageA = sbase + s * STAGE_BYTES;
        const uint32_t stageB = stageA + A_STAGE_BYTES;

#pragma unroll
        for (int ks = 0; ks < 4; ks++) {
            uint32_t afr[2][4];
            uint32_t bfr[4][2];
#pragma unroll
            for (int mt = 0; mt < 2; mt++)
                ldmatrix_x4(afr[mt][0], afr[mt][1], afr[mt][2], afr[mt][3],
                            stageA + swz(araw[mt] + ks * 32));
#pragma unroll
            for (int nt2 = 0; nt2 < 2; nt2++)
                ldmatrix_x4(bfr[nt2 * 2][0], bfr[nt2 * 2][1],
                            bfr[nt2 * 2 + 1][0], bfr[nt2 * 2 + 1][1],
                            stageB + swz(braw[nt2] + ks * 32));
#pragma unroll
            for (int mt = 0; mt < 2; mt++)
#pragma unroll
                for (int nt = 0; nt < 4; nt++)
                    mma_f16(acc[mt][nt][0], acc[mt][nt][1], acc[mt][nt][2], acc[mt][nt][3],
                            afr[mt][0], afr[mt][1], afr[mt][2], afr[mt][3],
                            bfr[nt][0], bfr[nt][1]);
        }
        if (++s == STAGES) s = 0;
    }

    // --- epilogue: += bias, fp32 stores ---
#pragma unroll
    for (int mt = 0; mt < 2; mt++) {
#pragma unroll
        for (int nt = 0; nt < 4; nt++) {
            int r = m0 + wm + mt * 16 + (lane >> 2);
            int c = n0 + wn + nt * 8 + (lane & 3) * 2;
            float2 bv = *reinterpret_cast<const float2*>(&bias[c]);
            float2 v0 = {acc[mt][nt][0] + bv.x, acc[mt][nt][1] + bv.y};
            float2 v1 = {acc[mt][nt][2] + bv.x, acc[mt][nt][3] + bv.y};
            *reinterpret_cast<float2*>(&out[(size_t)r * NDIM + c])       = v0;
            *reinterpret_cast<float2*>(&out[(size_t)(r + 8) * NDIM + c]) = v1;
        }
    }
}

// ========================= Launch =========================
extern "C" void kernel_launch(void* const* d_in, const int* in_sizes, int n_in,
                              void* d_out, int out_size) {
    const float* x    = (const float*)d_in[0];
    const int*   qw   = (const int*)d_in[1];
    const int*   qz   = (const int*)d_in[2];
    const float* sc   = (const float*)d_in[3];
    const float* bias = (const float*)d_in[4];
    float* out = (float*)d_out;

    // 1) merged prep: x->fp16 (first) || dequant W->fp16 (R10-measured order)
    prep_kernel<<<CONV_BLOCKS + DQ_BLOCKS, 256>>>(x, qw, qz, sc);

    // 2) fp16 GEMM (mma.sync), 3-stage, 3 CTAs/SM  [R10 winner verbatim]
    cudaFuncSetAttribute(gemm_f16_kernel,
                         cudaFuncAttributeMaxDynamicSharedMemorySize, GEMM_SMEM);
    dim3 grid(MDIM / BM, NDIM / BN);   // m-major for L2 reuse of A within wave
    gemm_f16_kernel<<<grid, 256, GEMM_SMEM>>>(bias, out);
}

// round 17
// speedup vs baseline: 1.4055x; 1.0020x over previous
#include <cuda_runtime.h>
#include <cuda_fp16.h>
#include <cstdint>

// Shapes (fixed for this problem)
constexpr int MDIM = 4096;   // B*S
constexpr int KDIM = 4096;
constexpr int NDIM = 11008;
constexpr int GRP  = 128;

// -----------------------------------------------------------------------
// Scratch (allocation-free rule: __device__ globals)
//   g_A: [M][K] fp16 = fp16(x)
//   g_B: [N][K] fp16 = fp16((v - z) * scale)   (k-contiguous rows)
// Single-fp16 GEMM error model: rel_err = 2.676e-4 (measured, bit-stable).
// -----------------------------------------------------------------------
__device__ __half g_A[(size_t)MDIM * KDIM];
__device__ __half g_B[(size_t)NDIM * KDIM];

// ========================= PTX helpers =========================
__device__ __forceinline__ uint32_t smem_u32(const void* p) {
    return (uint32_t)__cvta_generic_to_shared(p);
}
__device__ __forceinline__ void cp_async16(uint32_t smem, const void* gmem) {
    asm volatile("cp.async.cg.shared.global [%0], [%1], 16;\n"
                 :: "r"(smem), "l"(gmem));
}
__device__ __forceinline__ void cp_commit() {
    asm volatile("cp.async.commit_group;\n");
}
__device__ __forceinline__ void cp_wait1() {
    asm volatile("cp.async.wait_group 1;\n");
}
__device__ __forceinline__ void ldmatrix_x4(uint32_t& r0, uint32_t& r1,
                                            uint32_t& r2, uint32_t& r3,
                                            uint32_t addr) {
    asm volatile("ldmatrix.sync.aligned.m8n8.x4.shared.b16 {%0,%1,%2,%3}, [%4];\n"
                 : "=r"(r0), "=r"(r1), "=r"(r2), "=r"(r3) : "r"(addr));
}
__device__ __forceinline__ void mma_f16(float& c0, float& c1, float& c2, float& c3,
                                        uint32_t a0, uint32_t a1, uint32_t a2, uint32_t a3,
                                        uint32_t b0, uint32_t b1) {
    asm volatile("mma.sync.aligned.m16n8k16.row.col.f32.f16.f16.f32 "
                 "{%0,%1,%2,%3}, {%4,%5,%6,%7}, {%8,%9}, {%0,%1,%2,%3};\n"
                 : "+f"(c0), "+f"(c1), "+f"(c2), "+f"(c3)
                 : "r"(a0), "r"(a1), "r"(a2), "r"(a3), "r"(b0), "r"(b1));
}
// SW128-style swizzle on 128B rows: XOR bits [6:4] with bits [9:7]
__device__ __forceinline__ uint32_t swz(uint32_t o) {
    return o ^ ((o >> 3) & 0x70);
}

// ========================= Kernel 1: merged prep ========================
// Blocks [0, CONV_BLOCKS)          : x (fp32) -> g_A (fp16)  [DRAM-bound]
// Blocks [CONV_BLOCKS, +DQ_BLOCKS) : dequant W (256k x 64n)  [L2/compute]
// conv-first measured best: dequant compute overlaps conv's DRAM tail.
constexpr int CONV_BLOCKS = (MDIM * KDIM / 8) / 256;          // 8192
constexpr int DQ_NT = NDIM / 64;                               // 172
constexpr int DQ_KT = KDIM / 256;                              // 16
constexpr int DQ_BLOCKS = DQ_NT * DQ_KT;                       // 2752

constexpr int SH_STRIDE = 264;   // halfs per row (256 + 8 pad); chunk-swizzled

__global__ void prep_kernel(const float* __restrict__ x,
                            const int* __restrict__ qw,
                            const int* __restrict__ qz,
                            const float* __restrict__ sc) {
    const int tid = threadIdx.x;

    if (blockIdx.x < CONV_BLOCKS) {
        // ---- conv x -> fp16, 8 floats per thread ----
        size_t i = (size_t)blockIdx.x * 256 + tid;
        const float4* x4 = reinterpret_cast<const float4*>(x);
        float4 a = x4[2 * i];
        float4 b = x4[2 * i + 1];
        __half2 h0 = __floats2half2_rn(a.x, a.y);
        __half2 h1 = __floats2half2_rn(a.z, a.w);
        __half2 h2 = __floats2half2_rn(b.x, b.y);
        __half2 h3 = __floats2half2_rn(b.z, b.w);
        uint4 o;
        o.x = *reinterpret_cast<uint32_t*>(&h0);
        o.y = *reinterpret_cast<uint32_t*>(&h1);
        o.z = *reinterpret_cast<uint32_t*>(&h2);
        o.w = *reinterpret_cast<uint32_t*>(&h3);
        reinterpret_cast<uint4*>(g_A)[i] = o;
        return;
    }

    // ---- dequant W: tile 256 k x 64 n (two quant groups along k) ----
    // Per thread: packed col p (8 n's) x 8 consecutive k's -> 8x8 register
    // block -> 8 conflict-free STS.128 (chunk XOR swizzle).
    __shared__ __half sh[64 * SH_STRIDE];
    __shared__ float  s_scale[2][64];
    __shared__ int    s_z[2][8];

    const int t  = blockIdx.x - CONV_BLOCKS;
    const int n0 = (t % DQ_NT) * 64;
    const int k0 = (t / DQ_NT) * 256;
    const int g0 = k0 / GRP;
    const int pw = NDIM / 8;

    if (tid < 128) {
        int g  = tid >> 6;
        int nl = tid & 63;
        s_scale[g][nl] = sc[(size_t)(g0 + g) * NDIM + n0 + nl];
    }
    if (tid < 16) {
        s_z[tid >> 3][tid & 7] = qz[(size_t)(g0 + (tid >> 3)) * pw + n0 / 8 + (tid & 7)];
    }
    __syncthreads();

    const int p  = tid & 7;
    const int kq = tid >> 3;
    const int grp = kq >> 4;
    const int zp = s_z[grp][p];

    const int shifts[8] = {0, 16, 4, 20, 8, 24, 12, 28};
    float sc8[8];
    int   z8[8];
#pragma unroll
    for (int j = 0; j < 8; j++) {
        sc8[j] = s_scale[grp][p * 8 + j];
        z8[j]  = (zp >> shifts[j]) & 0xF;
    }

    __half rows[8][8];
#pragma unroll
    for (int d = 0; d < 8; d++) {
        int packed = qw[(size_t)(k0 + kq * 8 + d) * pw + n0 / 8 + p];
#pragma unroll
        for (int j = 0; j < 8; j++) {
            int v = (packed >> shifts[j]) & 0xF;
            rows[j][d] = __float2half_rn((float)(v - z8[j]) * sc8[j]);
        }
    }

    const int chnk = kq ^ p;
#pragma unroll
    for (int j = 0; j < 8; j++) {
        int row = p * 8 + j;
        *reinterpret_cast<uint4*>(&sh[row * SH_STRIDE + chnk * 8]) =
            *reinterpret_cast<const uint4*>(&rows[j][0]);
    }
    __syncthreads();

#pragma unroll
    for (int it = 0; it < 8; it++) {
        int u   = tid + it * 256;
        int row = u >> 5;
        int c   = u & 31;
        int cs  = c ^ ((row >> 3) & 7);
        uint4 v = *reinterpret_cast<const uint4*>(&sh[row * SH_STRIDE + cs * 8]);
        *reinterpret_cast<uint4*>(&g_B[(size_t)(n0 + row) * KDIM + k0 + c * 8]) = v;
    }
}

// ========================= Kernel 2: fp16 GEMM (mma.sync) ================
// Measured optimum (R10/R15/R16): BM=128 BN=64 BK=64, 8 warps (4m x 2n),
// 32x32 warp tile, swizzled smem, 3-stage cp.async, 3 CTAs/SM.
// tensor 75.2-75.4% = smem-crossbar cap at 0.172 B/MAC (measured == model).
// Grid packing is ideal: 5504 CTAs / 444 slots = 12.40 waves; measured
// GEMM time matches 12.40 x tile-wave within 0.2% (no tail slack).
constexpr int BM = 128, BN = 64, BK = 64;
constexpr int STAGES = 3;
constexpr int A_STAGE_BYTES = BM * BK * 2;     // 16384
constexpr int B_STAGE_BYTES = BN * BK * 2;     // 8192
constexpr int STAGE_BYTES = A_STAGE_BYTES + B_STAGE_BYTES;   // 24576
constexpr int GEMM_SMEM = STAGES * STAGE_BYTES;              // 73728

__global__ __launch_bounds__(256, 3)
void gemm_f16_kernel(const float* __restrict__ bias, float* __restrict__ out) {
    extern __shared__ __align__(128) uint8_t smem[];
    const uint32_t sbase = smem_u32(smem);

    const int tid  = threadIdx.x;
    const int lane = tid & 31;
    const int warp = tid >> 5;
    const int m0 = blockIdx.x * BM;       // m-major: wave covers all m tiles
    const int n0 = blockIdx.y * BN;
    const int wm = (warp & 3) * 32;       // 0/32/64/96
    const int wn = (warp >> 2) * 32;      // 0/32

    float acc[2][4][4];
#pragma unroll
    for (int a = 0; a < 2; a++)
#pragma unroll
        for (int b = 0; b < 4; b++)
#pragma unroll
            for (int c = 0; c < 4; c++) acc[a][b][c] = 0.0f;

    constexpr int T = KDIM / BK;  // 64

    // raw (pre-swizzle) per-lane ldmatrix offsets; swz applied after +ks*32
    uint32_t araw[2], braw[2];
#pragma unroll
    for (int mt = 0; mt < 2; mt++)
        araw[mt] = (uint32_t)(wm + mt * 16 + (lane & 15)) * 128 +
                   ((uint32_t)(lane >> 4) << 4);
#pragma unroll
    for (int nt2 = 0; nt2 < 2; nt2++)
        braw[nt2] = (uint32_t)(wn + nt2 * 16 + ((lane >> 4) << 3) + (lane & 7)) * 128 +
                    (((uint32_t)(lane >> 3) & 1) << 4);

    auto load_stage = [&](int s, int bk) {
        uint32_t Ab = sbase + s * STAGE_BYTES;
        uint32_t Bb = Ab + A_STAGE_BYTES;
#pragma unroll
        for (int i = 0; i < 4; i++) {
            int id = tid + i * 256;
            int r = id >> 3, c = id & 7;
            cp_async16(Ab + swz((uint32_t)r * 128 + (uint32_t)c * 16),
                       &g_A[(size_t)(m0 + r) * KDIM + bk + c * 8]);
        }
#pragma unroll
        for (int i = 0; i < 2; i++) {
            int id = tid + i * 256;
            int r = id >> 3, c = id & 7;
            cp_async16(Bb + swz((uint32_t)r * 128 + (uint32_t)c * 16),
                       &g_B[(size_t)(n0 + r) * KDIM + bk + c * 8]);
        }
    };

    load_stage(0, 0);  cp_commit();
    load_stage(1, BK); cp_commit();

    int s = 0;
    for (int t = 0; t < T; t++) {
        cp_wait1();          // stage t resident
        __syncthreads();     // overwritten slot provably consumed

        if (t + 2 < T) {
            int ns = s + 2;
            if (ns >= STAGES) ns -= STAGES;
            load_stage(ns, (t + 2) * BK);
        }
        cp_commit();

        const uint32_t stageA = sbase + s * STAGE_BYTES;
        const uint32_t stageB = stageA + A_STAGE_BYTES;

#pragma unroll
        for (int ks = 0; ks < 4; ks++) {
            uint32_t afr[2][4];
            uint32_t bfr[4][2];
#pragma unroll
            for (int mt = 0; mt < 2; mt++)
                ldmatrix_x4(afr[mt][0], afr[mt][1], afr[mt][2], afr[mt][3],
                            stageA + swz(araw[mt] + ks * 32));
#pragma unroll
            for (int nt2 = 0; nt2 < 2; nt2++)
                ldmatrix_x4(bfr[nt2 * 2][0], bfr[nt2 * 2][1],
                            bfr[nt2 * 2 + 1][0], bfr[nt2 * 2 + 1][1],
                            stageB + swz(braw[nt2] + ks * 32));
#pragma unroll
            for (int mt = 0; mt < 2; mt++)
#pragma unroll
                for (int nt = 0; nt < 4; nt++)
                    mma_f16(acc[mt][nt][0], acc[mt][nt][1], acc[mt][nt][2], acc[mt][nt][3],
                            afr[mt][0], afr[mt][1], afr[mt][2], afr[mt][3],
                            bfr[nt][0], bfr[nt][1]);
        }
        if (++s == STAGES) s = 0;
    }

    // --- epilogue: += bias, fp32 stores ---
#pragma unroll
    for (int mt = 0; mt < 2; mt++) {
#pragma unroll
        for (int nt = 0; nt < 4; nt++) {
            int r = m0 + wm + mt * 16 + (lane >> 2);
            int c = n0 + wn + nt * 8 + (lane & 3) * 2;
            float2 bv = *reinterpret_cast<const float2*>(&bias[c]);
            float2 v0 = {acc[mt][nt][0] + bv.x, acc[mt][nt][1] + bv.y};
            float2 v1 = {acc[mt][nt][2] + bv.x, acc[mt][nt][3] + bv.y};
            *reinterpret_cast<float2*>(&out[(size_t)r * NDIM + c])       = v0;
            *reinterpret_cast<float2*>(&out[(size_t)(r + 8) * NDIM + c]) = v1;
        }
    }
}

// ========================= Launch =========================
extern "C" void kernel_launch(void* const* d_in, const int* in_sizes, int n_in,
                              void* d_out, int out_size) {
    const float* x    = (const float*)d_in[0];
    const int*   qw   = (const int*)d_in[1];
    const int*   qz   = (const int*)d_in[2];
    const float* sc   = (const float*)d_in[3];
    const float* bias = (const float*)d_in[4];
    float* out = (float*)d_out;

    // 1) merged prep: x->fp16 (first) || dequant W->fp16 (measured order)
    prep_kernel<<<CONV_BLOCKS + DQ_BLOCKS, 256>>>(x, qw, qz, sc);

    // 2) fp16 GEMM (mma.sync), 3-stage, 3 CTAs/SM  [measured optimum]
    cudaFuncSetAttribute(gemm_f16_kernel,
                         cudaFuncAttributeMaxDynamicSharedMemorySize, GEMM_SMEM);
    dim3 grid(MDIM / BM, NDIM / BN);   // m-major for L2 reuse of A within wave
    gemm_f16_kernel<<<grid, 256, GEMM_SMEM>>>(bias, out);
}